// round 2
// baseline (speedup 1.0000x reference)
#include <cuda_runtime.h>
#include <math.h>

#define BSZ  16      // batch
#define NCAP 1152    // primary caps
#define DP   8       // dim primary
#define DDIG 10      // digit caps
#define DD   16      // dim digit

#define TILE_N 64
#define NT (NCAP / TILE_N)   // 18

// Scratch (device globals; no allocation allowed)
__device__ float g_U[BSZ * DDIG * NCAP * DD];   // U_hat [b][d][n][j]  ~11.8 MB
__device__ float g_Asum[BSZ * DDIG * NCAP];     // A_sum [b][d][n]     ~0.74 MB

// -------------------------------------------------------------------------
// K1: votes  U_hat[b,d,n,j] = sum_i W[d,n,j,i] * u[b,n,i]
// Grid: (DDIG, NT). Each CTA handles one d and a 64-wide n tile, ALL 16 b.
// W is read exactly once from DRAM (5.9 MB total); u staged in SMEM.
// -------------------------------------------------------------------------
__global__ __launch_bounds__(256) void k1_votes(
    const float* __restrict__ u,   // [B][N][DP]
    const float* __restrict__ W)   // [D][N][DD][DP]
{
    const int d  = blockIdx.x;
    const int n0 = blockIdx.y * TILE_N;
    const int t  = threadIdx.x;

    __shared__ __align__(16) float us[BSZ][TILE_N][DP];   // 32 KB

    // Stage u tile: 16 * 64 * 8 floats = 2048 float4
    for (int idx = t; idx < BSZ * TILE_N * DP / 4; idx += 256) {
        const int b   = idx >> 7;       // 128 float4 per b
        const int rem = idx & 127;
        const float4 v = reinterpret_cast<const float4*>(
            u + (size_t)b * NCAP * DP + (size_t)n0 * DP)[rem];
        reinterpret_cast<float4*>(&us[b][0][0])[rem] = v;
    }
    __syncthreads();

    // Work items: (n_local, j) pairs = 64*16 = 1024; 4 per thread.
    #pragma unroll
    for (int it = 0; it < (TILE_N * DD) / 256; ++it) {
        const int idx = it * 256 + t;
        const int j   = idx & 15;
        const int nl  = idx >> 4;
        const int n   = n0 + nl;

        const float4* wp = reinterpret_cast<const float4*>(
            W + ((size_t)(d * NCAP + n) * DD + j) * DP);
        const float4 w0 = wp[0];
        const float4 w1 = wp[1];

        #pragma unroll
        for (int b = 0; b < BSZ; ++b) {
            const float4* up = reinterpret_cast<const float4*>(&us[b][nl][0]);
            const float4 u0 = up[0];
            const float4 u1 = up[1];
            float acc = w0.x * u0.x + w0.y * u0.y + w0.z * u0.z + w0.w * u0.w
                      + w1.x * u1.x + w1.y * u1.y + w1.z * u1.z + w1.w * u1.w;
            g_U[((size_t)(b * DDIG + d) * NCAP + n) * DD + j] = acc;
        }
    }
}

// -------------------------------------------------------------------------
// K2: per (b,d): T[j] = sum_n U[n][j], then A_sum[n] = (T . U[n]) / sqrt(8)
// Grid: (DDIG, BSZ)
// -------------------------------------------------------------------------
__global__ __launch_bounds__(256) void k2_asum()
{
    const int d = blockIdx.x;
    const int b = blockIdx.y;
    const int t = threadIdx.x;

    const float* Ubd = g_U + (size_t)(b * DDIG + d) * NCAP * DD;

    float part[DD];
    #pragma unroll
    for (int j = 0; j < DD; ++j) part[j] = 0.f;

    for (int n = t; n < NCAP; n += 256) {
        const float4* r = reinterpret_cast<const float4*>(Ubd + (size_t)n * DD);
        const float4 v0 = r[0], v1 = r[1], v2 = r[2], v3 = r[3];
        part[0]  += v0.x; part[1]  += v0.y; part[2]  += v0.z; part[3]  += v0.w;
        part[4]  += v1.x; part[5]  += v1.y; part[6]  += v1.z; part[7]  += v1.w;
        part[8]  += v2.x; part[9]  += v2.y; part[10] += v2.z; part[11] += v2.w;
        part[12] += v3.x; part[13] += v3.y; part[14] += v3.z; part[15] += v3.w;
    }

    // warp reduce 16 lanes-worth of partials
    #pragma unroll
    for (int off = 16; off > 0; off >>= 1) {
        #pragma unroll
        for (int j = 0; j < DD; ++j)
            part[j] += __shfl_xor_sync(0xffffffffu, part[j], off);
    }

    __shared__ float wsum[8][DD];
    const int lane = t & 31, w = t >> 5;
    if (lane == 0) {
        #pragma unroll
        for (int j = 0; j < DD; ++j) wsum[w][j] = part[j];
    }
    __syncthreads();

    __shared__ float Tsh[DD];
    if (t < DD) {
        float s = 0.f;
        #pragma unroll
        for (int ww = 0; ww < 8; ++ww) s += wsum[ww][t];
        Tsh[t] = s;
    }
    __syncthreads();

    float T[DD];
    #pragma unroll
    for (int j = 0; j < DD; ++j) T[j] = Tsh[j];

    const float inv_sqrt8 = 0.3535533905932738f;
    float* As = g_Asum + (size_t)(b * DDIG + d) * NCAP;
    for (int n = t; n < NCAP; n += 256) {
        const float4* r = reinterpret_cast<const float4*>(Ubd + (size_t)n * DD);
        const float4 v0 = r[0], v1 = r[1], v2 = r[2], v3 = r[3];
        float dot = T[0]  * v0.x + T[1]  * v0.y + T[2]  * v0.z + T[3]  * v0.w
                  + T[4]  * v1.x + T[5]  * v1.y + T[6]  * v1.z + T[7]  * v1.w
                  + T[8]  * v2.x + T[9]  * v2.y + T[10] * v2.z + T[11] * v2.w
                  + T[12] * v3.x + T[13] * v3.y + T[14] * v3.z + T[15] * v3.w;
        As[n] = dot * inv_sqrt8;
    }
}

// -------------------------------------------------------------------------
// K3: softmax over d (per b,n), S[b,d,j] = sum_n (B_prior[d,n] + C[b,d,n]) * U[b,d,n,j]
// then squash. Grid: (DDIG, BSZ)
// -------------------------------------------------------------------------
__global__ __launch_bounds__(256) void k3_out(
    const float* __restrict__ Bp,   // [D][1][N]
    float* __restrict__ out)        // [B][D][DD]
{
    const int d = blockIdx.x;
    const int b = blockIdx.y;
    const int t = threadIdx.x;

    const float* Ubd = g_U + (size_t)(b * DDIG + d) * NCAP * DD;
    const float* As  = g_Asum + (size_t)b * DDIG * NCAP;

    float s[DD];
    #pragma unroll
    for (int j = 0; j < DD; ++j) s[j] = 0.f;

    for (int n = t; n < NCAP; n += 256) {
        float a[DDIG];
        float m = -1e30f;
        #pragma unroll
        for (int dd = 0; dd < DDIG; ++dd) {
            a[dd] = As[(size_t)dd * NCAP + n];
            m = fmaxf(m, a[dd]);
        }
        float denom = 0.f;
        #pragma unroll
        for (int dd = 0; dd < DDIG; ++dd) denom += expf(a[dd] - m);
        const float c   = expf(a[d] - m) / denom;
        const float wgt = c + Bp[(size_t)d * NCAP + n];

        const float4* r = reinterpret_cast<const float4*>(Ubd + (size_t)n * DD);
        const float4 v0 = r[0], v1 = r[1], v2 = r[2], v3 = r[3];
        s[0]  += wgt * v0.x; s[1]  += wgt * v0.y; s[2]  += wgt * v0.z; s[3]  += wgt * v0.w;
        s[4]  += wgt * v1.x; s[5]  += wgt * v1.y; s[6]  += wgt * v1.z; s[7]  += wgt * v1.w;
        s[8]  += wgt * v2.x; s[9]  += wgt * v2.y; s[10] += wgt * v2.z; s[11] += wgt * v2.w;
        s[12] += wgt * v3.x; s[13] += wgt * v3.y; s[14] += wgt * v3.z; s[15] += wgt * v3.w;
    }

    #pragma unroll
    for (int off = 16; off > 0; off >>= 1) {
        #pragma unroll
        for (int j = 0; j < DD; ++j)
            s[j] += __shfl_xor_sync(0xffffffffu, s[j], off);
    }

    __shared__ float wsum[8][DD];
    const int lane = t & 31, w = t >> 5;
    if (lane == 0) {
        #pragma unroll
        for (int j = 0; j < DD; ++j) wsum[w][j] = s[j];
    }
    __syncthreads();

    __shared__ float Sf[DD];
    __shared__ float coef_sh;
    if (t < DD) {
        float v = 0.f;
        #pragma unroll
        for (int ww = 0; ww < 8; ++ww) v += wsum[ww][t];
        Sf[t] = v;
    }
    __syncthreads();
    if (t == 0) {
        float nn = 0.f;
        #pragma unroll
        for (int j = 0; j < DD; ++j) nn += Sf[j] * Sf[j];
        const float norm = sqrtf(nn);
        const float EPS  = 1e-7f;
        coef_sh = (1.f - 1.f / (expf(norm) + EPS)) / (norm + EPS);
    }
    __syncthreads();
    if (t < DD) {
        out[(size_t)(b * DDIG + d) * DD + t] = coef_sh * Sf[t];
    }
}

// -------------------------------------------------------------------------
extern "C" void kernel_launch(void* const* d_in, const int* in_sizes, int n_in,
                              void* d_out, int out_size)
{
    const float* u  = (const float*)d_in[0];   // primary_caps [16,1152,8]
    const float* W  = (const float*)d_in[1];   // W            [10,1152,16,8]
    const float* Bp = (const float*)d_in[2];   // B_prior      [10,1,1152]
    float* out      = (float*)d_out;           // [16,10,16]

    (void)in_sizes; (void)n_in; (void)out_size;

    k1_votes<<<dim3(DDIG, NT), 256>>>(u, W);
    k2_asum<<<dim3(DDIG, BSZ), 256>>>();
    k3_out<<<dim3(DDIG, BSZ), 256>>>(Bp, out);
}